// round 1
// baseline (speedup 1.0000x reference)
#include <cuda_runtime.h>
#include <cuda_bf16.h>
#include <math.h>

// Problem constants
#define BATCH 8192
#define HID   1024
#define FH    96
#define O_DIM 8
#define E_DIM 36            // O + O*(O-1)/2 = 8 + 28
#define NM    (FH * O_DIM)  // 768
#define NV    (FH * E_DIM)  // 3456

// Scratch (device globals: allocation-free per harness rules)
__device__ float g_inter[(size_t)BATCH * HID];   // silu(z@W1+b1)
__device__ float g_h[(size_t)BATCH * HID];       // h
__device__ float g_lv[(size_t)BATCH * NV];       // log_var (pre-reshape)

// ---------------------------------------------------------------------------
// SGEMM: C[M,N] = act(A[M,K] @ B[K,N] + bias[N])
// BM=BN=128, BK=8, TM=TN=8, 256 threads. All dims assumed multiples of tiles.
// ---------------------------------------------------------------------------
template <bool SILU>
__global__ __launch_bounds__(256, 2)
void sgemm_bias(int M, int N, int K,
                const float* __restrict__ A,
                const float* __restrict__ B,
                const float* __restrict__ bias,
                float* __restrict__ C)
{
    constexpr int BM = 128, BN = 128, BK = 8, TM = 8, TN = 8;
    __shared__ float As[BK][BM];
    __shared__ float Bs[BK][BN];

    const int tid = threadIdx.x;
    const int tx = tid % 16;           // 16 threads across N
    const int ty = tid / 16;           // 16 threads across M
    const int bx = blockIdx.x;         // N tile
    const int by = blockIdx.y;         // M tile

    // A tile load mapping: 128 rows x 8 cols = 1024 floats, float4 per thread
    const int aRow  = tid >> 1;          // 0..127
    const int aCol4 = (tid & 1) * 4;     // 0 or 4
    // B tile load mapping: 8 rows x 128 cols
    const int bRow  = tid >> 5;          // 0..7
    const int bCol4 = (tid & 31) * 4;    // 0..124

    const float* Ablk = A + (size_t)(by * BM) * K;
    const float* Bblk = B + (size_t)(bx * BN);

    float acc[TM][TN];
#pragma unroll
    for (int i = 0; i < TM; i++)
#pragma unroll
        for (int j = 0; j < TN; j++) acc[i][j] = 0.f;

    for (int k0 = 0; k0 < K; k0 += BK) {
        float4 a = *(const float4*)(Ablk + (size_t)aRow * K + k0 + aCol4);
        As[aCol4 + 0][aRow] = a.x;
        As[aCol4 + 1][aRow] = a.y;
        As[aCol4 + 2][aRow] = a.z;
        As[aCol4 + 3][aRow] = a.w;
        *(float4*)&Bs[bRow][bCol4] =
            *(const float4*)(Bblk + (size_t)(k0 + bRow) * N + bCol4);
        __syncthreads();

#pragma unroll
        for (int kk = 0; kk < BK; kk++) {
            float ar[TM], br[TN];
#pragma unroll
            for (int i = 0; i < TM; i++) ar[i] = As[kk][ty * TM + i];
#pragma unroll
            for (int j = 0; j < TN; j++) br[j] = Bs[kk][tx * TN + j];
#pragma unroll
            for (int i = 0; i < TM; i++)
#pragma unroll
                for (int j = 0; j < TN; j++) acc[i][j] = fmaf(ar[i], br[j], acc[i][j]);
        }
        __syncthreads();
    }

    // Epilogue: bias + optional SiLU, vectorized stores
    const int colBase = bx * BN + tx * TN;
#pragma unroll
    for (int i = 0; i < TM; i++) {
        const int row = by * BM + ty * TM + i;
        float* crow = C + (size_t)row * N + colBase;
#pragma unroll
        for (int j = 0; j < TN; j += 4) {
            float4 v;
            v.x = acc[i][j + 0] + bias[colBase + j + 0];
            v.y = acc[i][j + 1] + bias[colBase + j + 1];
            v.z = acc[i][j + 2] + bias[colBase + j + 2];
            v.w = acc[i][j + 3] + bias[colBase + j + 3];
            if (SILU) {
                v.x = v.x / (1.f + expf(-v.x));
                v.y = v.y / (1.f + expf(-v.y));
                v.z = v.z / (1.f + expf(-v.z));
                v.w = v.w / (1.f + expf(-v.w));
            }
            *(float4*)(crow + j) = v;
        }
    }
}

// ---------------------------------------------------------------------------
// Epilogue: per (b,h) group of O=8: read eta[36], emit precision/D/T (8x8 each)
// 64 threads per group, 4 groups per 256-thread block.
// ---------------------------------------------------------------------------
__device__ __forceinline__ int triu_idx(int r, int c) {
    // index into the 28 strict-upper entries, row-major (numpy triu_indices order)
    return r * (15 - r) / 2 + (c - r - 1);
}

__global__ __launch_bounds__(256)
void mvn_epilogue(const float* __restrict__ lv,
                  float* __restrict__ prec,
                  float* __restrict__ Dout,
                  float* __restrict__ Tout)
{
    constexpr int GP = 4;
    __shared__ float s_eta[GP][E_DIM];
    __shared__ float s_d[GP][O_DIM];
    __shared__ float s_dinv[GP][O_DIM];

    const int g  = threadIdx.x >> 6;   // group within block
    const int t  = threadIdx.x & 63;   // 0..63
    const size_t bh = (size_t)blockIdx.x * GP + g;

    if (t < E_DIM) s_eta[g][t] = lv[bh * E_DIM + t];
    __syncthreads();
    if (t < O_DIM) {
        float d = expf(0.5f * s_eta[g][t]);
        s_d[g][t]    = d;
        s_dinv[g][t] = 1.f / d;
    }
    __syncthreads();

    const int i = t >> 3;   // row index into output matrix
    const int k = t & 7;    // col index

    const float* e = s_eta[g];
    const float* dinv = s_dinv[g];

    // T[i][k]
    float tv = (i == k) ? 1.f : ((i < k) ? e[O_DIM + triu_idx(i, k)] : 0.f);
    // D[i][k]
    float dv = (i == k) ? s_d[g][i] : 0.f;
    // precision[i][k] = sum_j T[j][i] * T[j][k] * dinv[j]
    float s = 0.f;
#pragma unroll
    for (int j = 0; j < O_DIM; j++) {
        float tji = (j == i) ? 1.f : ((j < i) ? e[O_DIM + triu_idx(j, i)] : 0.f);
        float tjk = (j == k) ? 1.f : ((j < k) ? e[O_DIM + triu_idx(j, k)] : 0.f);
        s = fmaf(tji * tjk, dinv[j], s);
    }

    const size_t base = bh * (O_DIM * O_DIM) + t;
    prec[base] = s;
    Dout[base] = dv;
    Tout[base] = tv;
}

// ---------------------------------------------------------------------------
// Launch
// ---------------------------------------------------------------------------
extern "C" void kernel_launch(void* const* d_in, const int* in_sizes, int n_in,
                              void* d_out, int out_size)
{
    const float* z  = (const float*)d_in[0];
    const float* W1 = (const float*)d_in[1];
    const float* b1 = (const float*)d_in[2];
    const float* W2 = (const float*)d_in[3];
    const float* b2 = (const float*)d_in[4];
    const float* Wm = (const float*)d_in[5];
    const float* bm = (const float*)d_in[6];
    const float* Wv = (const float*)d_in[7];
    const float* bv = (const float*)d_in[8];

    float* out = (float*)d_out;
    const size_t n_means = (size_t)BATCH * FH * O_DIM;                  // 6,291,456
    const size_t n_mat   = (size_t)BATCH * FH * O_DIM * O_DIM;          // 50,331,648
    float* means = out;
    float* prec  = out + n_means;
    float* Dout  = prec + n_mat;
    float* Tout  = Dout + n_mat;

    float* inter; cudaGetSymbolAddress((void**)&inter, g_inter);
    float* h;     cudaGetSymbolAddress((void**)&h, g_h);
    float* lv;    cudaGetSymbolAddress((void**)&lv, g_lv);

    dim3 blk(256);

    // 1) inter = silu(z @ W1 + b1)      [8192,1024]
    sgemm_bias<true ><<<dim3(HID / 128, BATCH / 128), blk>>>(BATCH, HID, HID, z, W1, b1, inter);
    // 2) h = inter @ W2 + b2            [8192,1024]
    sgemm_bias<false><<<dim3(HID / 128, BATCH / 128), blk>>>(BATCH, HID, HID, inter, W2, b2, h);
    // 3) means = h @ Wm + bm            [8192,768] -> directly into d_out
    sgemm_bias<false><<<dim3(NM / 128, BATCH / 128), blk>>>(BATCH, NM, HID, h, Wm, bm, means);
    // 4) lv = h @ Wv + bv               [8192,3456]
    sgemm_bias<false><<<dim3(NV / 128, BATCH / 128), blk>>>(BATCH, NV, HID, h, Wv, bv, lv);
    // 5) precision / D / T epilogue     (B*FH = 786432 groups, 4 per block)
    mvn_epilogue<<<(BATCH * FH) / 4, blk>>>(lv, prec, Dout, Tout);
}

// round 2
// speedup vs baseline: 1.7813x; 1.7813x over previous
#include <cuda_runtime.h>
#include <cuda_bf16.h>
#include <math.h>
#include <stdint.h>

// Problem constants
#define BATCH 8192
#define HID   1024
#define FH    96
#define O_DIM 8
#define E_DIM 36            // O + O*(O-1)/2
#define NM    (FH * O_DIM)  // 768
#define NV    (FH * E_DIM)  // 3456

// Scratch (device globals: allocation-free per harness rules)
__device__ float g_inter[(size_t)BATCH * HID];
__device__ float g_h[(size_t)BATCH * HID];
__device__ float g_lv[(size_t)BATCH * NV];

// ---------------------------------------------------------------------------
// helpers
// ---------------------------------------------------------------------------
__device__ __forceinline__ uint32_t pack_split(float x0, float x1, uint32_t& lo_pack)
{
    __nv_bfloat16 h0 = __float2bfloat16(x0);
    __nv_bfloat16 h1 = __float2bfloat16(x1);
    float r0 = x0 - __bfloat162float(h0);
    float r1 = x1 - __bfloat162float(h1);
    __nv_bfloat162 hp = __halves2bfloat162(h0, h1);
    __nv_bfloat162 lp = __halves2bfloat162(__float2bfloat16(r0), __float2bfloat16(r1));
    lo_pack = *reinterpret_cast<uint32_t*>(&lp);
    return *reinterpret_cast<uint32_t*>(&hp);
}

__device__ __forceinline__ void mma16816(float* d, const uint32_t* a, const uint32_t* b)
{
    asm volatile(
        "mma.sync.aligned.m16n8k16.row.col.f32.bf16.bf16.f32 "
        "{%0,%1,%2,%3},{%4,%5,%6,%7},{%8,%9},{%0,%1,%2,%3};\n"
        : "+f"(d[0]), "+f"(d[1]), "+f"(d[2]), "+f"(d[3])
        : "r"(a[0]), "r"(a[1]), "r"(a[2]), "r"(a[3]), "r"(b[0]), "r"(b[1]));
}

// ---------------------------------------------------------------------------
// bf16x3 split-precision GEMM: C[M,N] = act(A[M,K] @ B[K,N] + bias[N])
// CTA tile 128x128, BK=16. 8 warps: 4 (M) x 2 (N), each 32x64.
// MMA m16n8k16 bf16, fp32 accum; 3 passes (hi*hi + hi*lo + lo*hi).
// Requires M%128==0, N%128==0, K%16==0.
// ---------------------------------------------------------------------------
template <bool SILU>
__global__ __launch_bounds__(256)
void gemm_bf16x3(int M, int N, int K,
                 const float* __restrict__ A,
                 const float* __restrict__ B,
                 const float* __restrict__ bias,
                 float* __restrict__ C)
{
    constexpr int BM = 128, BN = 128, BK = 16;
    constexpr int AS = BK / 2 + 1;     // 9 b32 per row (pad kills bank conflicts)

    __shared__ uint32_t sAhi[2][BM * AS];
    __shared__ uint32_t sAlo[2][BM * AS];
    __shared__ uint32_t sBhi[2][BN * AS];
    __shared__ uint32_t sBlo[2][BN * AS];

    const int tid  = threadIdx.x;
    const int lane = tid & 31;
    const int warp = tid >> 5;
    const int g = lane >> 2;           // 0..7
    const int t = lane & 3;            // 0..3
    const int warpM = warp & 3;        // 4 warps along M
    const int warpN = warp >> 2;       // 2 warps along N
    const int m0 = warpM * 32;
    const int n0 = warpN * 64;

    const int blockM = blockIdx.y * BM;
    const int blockN = blockIdx.x * BN;

    // Global load mapping
    const int am  = tid >> 1;          // A row within tile: 0..127
    const int ak  = (tid & 1) * 8;     // A k offset: 0 or 8
    const int bkp = tid >> 5;          // B k-pair: 0..7
    const int bn  = (tid & 31) * 4;    // B n offset: 0..124

    const float* Ag  = A + (size_t)(blockM + am) * K + ak;
    const float* Bg0 = B + (size_t)(2 * bkp) * N + blockN + bn;
    const float* Bg1 = Bg0 + N;

    float acc[2][8][4];
#pragma unroll
    for (int i = 0; i < 2; i++)
#pragma unroll
        for (int j = 0; j < 8; j++)
#pragma unroll
            for (int c = 0; c < 4; c++) acc[i][j][c] = 0.f;

    float ar[8], br0[4], br1[4];

    const int nIter = K / BK;

    // --- prologue: load tile 0 ---
    {
        float4 a0 = *(const float4*)(Ag);
        float4 a1 = *(const float4*)(Ag + 4);
        ar[0]=a0.x; ar[1]=a0.y; ar[2]=a0.z; ar[3]=a0.w;
        ar[4]=a1.x; ar[5]=a1.y; ar[6]=a1.z; ar[7]=a1.w;
        float4 b0 = *(const float4*)(Bg0);
        float4 b1 = *(const float4*)(Bg1);
        br0[0]=b0.x; br0[1]=b0.y; br0[2]=b0.z; br0[3]=b0.w;
        br1[0]=b1.x; br1[1]=b1.y; br1[2]=b1.z; br1[3]=b1.w;
    }
    // store tile 0 into buffer 0
    {
#pragma unroll
        for (int j = 0; j < 4; j++) {
            uint32_t lo, hi = pack_split(ar[2*j], ar[2*j+1], lo);
            int idx = am * AS + (ak >> 1) + j;
            sAhi[0][idx] = hi; sAlo[0][idx] = lo;
        }
#pragma unroll
        for (int n = 0; n < 4; n++) {
            uint32_t lo, hi = pack_split(br0[n], br1[n], lo);
            int idx = (bn + n) * AS + bkp;
            sBhi[0][idx] = hi; sBlo[0][idx] = lo;
        }
    }
    __syncthreads();

    for (int it = 0; it < nIter; ++it) {
        const int p = it & 1;

        // prefetch next tile into registers (LDGs overlap with MMA below)
        if (it + 1 < nIter) {
            const float* ap  = Ag  + (size_t)(it + 1) * BK;
            const float* bp0 = Bg0 + (size_t)(it + 1) * BK * N;
            const float* bp1 = Bg1 + (size_t)(it + 1) * BK * N;
            float4 a0 = *(const float4*)(ap);
            float4 a1 = *(const float4*)(ap + 4);
            ar[0]=a0.x; ar[1]=a0.y; ar[2]=a0.z; ar[3]=a0.w;
            ar[4]=a1.x; ar[5]=a1.y; ar[6]=a1.z; ar[7]=a1.w;
            float4 b0 = *(const float4*)(bp0);
            float4 b1 = *(const float4*)(bp1);
            br0[0]=b0.x; br0[1]=b0.y; br0[2]=b0.z; br0[3]=b0.w;
            br1[0]=b1.x; br1[1]=b1.y; br1[2]=b1.z; br1[3]=b1.w;
        }

        // load fragments from smem buffer p
        uint32_t fAhi[2][4], fAlo[2][4], fBhi[8][2], fBlo[8][2];
#pragma unroll
        for (int mt = 0; mt < 2; mt++) {
            const int r = m0 + mt * 16;
            fAhi[mt][0] = sAhi[p][(r + g    ) * AS + t    ];
            fAhi[mt][1] = sAhi[p][(r + g + 8) * AS + t    ];
            fAhi[mt][2] = sAhi[p][(r + g    ) * AS + t + 4];
            fAhi[mt][3] = sAhi[p][(r + g + 8) * AS + t + 4];
            fAlo[mt][0] = sAlo[p][(r + g    ) * AS + t    ];
            fAlo[mt][1] = sAlo[p][(r + g + 8) * AS + t    ];
            fAlo[mt][2] = sAlo[p][(r + g    ) * AS + t + 4];
            fAlo[mt][3] = sAlo[p][(r + g + 8) * AS + t + 4];
        }
#pragma unroll
        for (int nt = 0; nt < 8; nt++) {
            const int c = n0 + nt * 8;
            fBhi[nt][0] = sBhi[p][(c + g) * AS + t    ];
            fBhi[nt][1] = sBhi[p][(c + g) * AS + t + 4];
            fBlo[nt][0] = sBlo[p][(c + g) * AS + t    ];
            fBlo[nt][1] = sBlo[p][(c + g) * AS + t + 4];
        }

        // 3-pass split-precision MMA
#pragma unroll
        for (int mt = 0; mt < 2; mt++)
#pragma unroll
            for (int nt = 0; nt < 8; nt++) {
                mma16816(acc[mt][nt], fAhi[mt], fBhi[nt]);
                mma16816(acc[mt][nt], fAhi[mt], fBlo[nt]);
                mma16816(acc[mt][nt], fAlo[mt], fBhi[nt]);
            }

        // store prefetched tile into the other buffer
        if (it + 1 < nIter) {
            const int q = (it + 1) & 1;
#pragma unroll
            for (int j = 0; j < 4; j++) {
                uint32_t lo, hi = pack_split(ar[2*j], ar[2*j+1], lo);
                int idx = am * AS + (ak >> 1) + j;
                sAhi[q][idx] = hi; sAlo[q][idx] = lo;
            }
#pragma unroll
            for (int n = 0; n < 4; n++) {
                uint32_t lo, hi = pack_split(br0[n], br1[n], lo);
                int idx = (bn + n) * AS + bkp;
                sBhi[q][idx] = hi; sBlo[q][idx] = lo;
            }
        }
        __syncthreads();
    }

    // epilogue: bias + optional SiLU
#pragma unroll
    for (int mt = 0; mt < 2; mt++) {
        const int row0 = blockM + m0 + mt * 16 + g;
#pragma unroll
        for (int nt = 0; nt < 8; nt++) {
            const int col = blockN + n0 + nt * 8 + 2 * t;
            const float bv0 = bias[col], bv1 = bias[col + 1];
            float2 v0, v1;
            v0.x = acc[mt][nt][0] + bv0; v0.y = acc[mt][nt][1] + bv1;
            v1.x = acc[mt][nt][2] + bv0; v1.y = acc[mt][nt][3] + bv1;
            if (SILU) {
                v0.x = v0.x / (1.f + expf(-v0.x));
                v0.y = v0.y / (1.f + expf(-v0.y));
                v1.x = v1.x / (1.f + expf(-v1.x));
                v1.y = v1.y / (1.f + expf(-v1.y));
            }
            *(float2*)(C + (size_t)row0 * N + col)       = v0;
            *(float2*)(C + (size_t)(row0 + 8) * N + col) = v1;
        }
    }
}

// ---------------------------------------------------------------------------
// Epilogue: per (b,h) group: read eta[36], emit precision/D/T (8x8 each)
// ---------------------------------------------------------------------------
__device__ __forceinline__ int triu_idx(int r, int c) {
    return r * (15 - r) / 2 + (c - r - 1);
}

__global__ __launch_bounds__(256)
void mvn_epilogue(const float* __restrict__ lv,
                  float* __restrict__ prec,
                  float* __restrict__ Dout,
                  float* __restrict__ Tout)
{
    constexpr int GP = 4;
    __shared__ float s_eta[GP][E_DIM];
    __shared__ float s_d[GP][O_DIM];
    __shared__ float s_dinv[GP][O_DIM];

    const int g  = threadIdx.x >> 6;
    const int t  = threadIdx.x & 63;
    const size_t bh = (size_t)blockIdx.x * GP + g;

    if (t < E_DIM) s_eta[g][t] = lv[bh * E_DIM + t];
    __syncthreads();
    if (t < O_DIM) {
        float d = expf(0.5f * s_eta[g][t]);
        s_d[g][t]    = d;
        s_dinv[g][t] = 1.f / d;
    }
    __syncthreads();

    const int i = t >> 3;
    const int k = t & 7;
    const float* e = s_eta[g];
    const float* dinv = s_dinv[g];

    float tv = (i == k) ? 1.f : ((i < k) ? e[O_DIM + triu_idx(i, k)] : 0.f);
    float dv = (i == k) ? s_d[g][i] : 0.f;
    float s = 0.f;
#pragma unroll
    for (int j = 0; j < O_DIM; j++) {
        float tji = (j == i) ? 1.f : ((j < i) ? e[O_DIM + triu_idx(j, i)] : 0.f);
        float tjk = (j == k) ? 1.f : ((j < k) ? e[O_DIM + triu_idx(j, k)] : 0.f);
        s = fmaf(tji * tjk, dinv[j], s);
    }

    const size_t base = bh * (O_DIM * O_DIM) + t;
    prec[base] = s;
    Dout[base] = dv;
    Tout[base] = tv;
}

// ---------------------------------------------------------------------------
// Launch
// ---------------------------------------------------------------------------
extern "C" void kernel_launch(void* const* d_in, const int* in_sizes, int n_in,
                              void* d_out, int out_size)
{
    const float* z  = (const float*)d_in[0];
    const float* W1 = (const float*)d_in[1];
    const float* b1 = (const float*)d_in[2];
    const float* W2 = (const float*)d_in[3];
    const float* b2 = (const float*)d_in[4];
    const float* Wm = (const float*)d_in[5];
    const float* bm = (const float*)d_in[6];
    const float* Wv = (const float*)d_in[7];
    const float* bv = (const float*)d_in[8];

    float* out = (float*)d_out;
    const size_t n_means = (size_t)BATCH * FH * O_DIM;
    const size_t n_mat   = (size_t)BATCH * FH * O_DIM * O_DIM;
    float* means = out;
    float* prec  = out + n_means;
    float* Dout  = prec + n_mat;
    float* Tout  = Dout + n_mat;

    float* inter; cudaGetSymbolAddress((void**)&inter, g_inter);
    float* h;     cudaGetSymbolAddress((void**)&h, g_h);
    float* lv;    cudaGetSymbolAddress((void**)&lv, g_lv);

    dim3 blk(256);

    gemm_bf16x3<true ><<<dim3(HID / 128, BATCH / 128), blk>>>(BATCH, HID, HID, z, W1, b1, inter);
    gemm_bf16x3<false><<<dim3(HID / 128, BATCH / 128), blk>>>(BATCH, HID, HID, inter, W2, b2, h);
    gemm_bf16x3<false><<<dim3(NM  / 128, BATCH / 128), blk>>>(BATCH, NM,  HID, h, Wm, bm, means);
    gemm_bf16x3<false><<<dim3(NV  / 128, BATCH / 128), blk>>>(BATCH, NV,  HID, h, Wv, bv, lv);
    mvn_epilogue<<<(BATCH * FH) / 4, blk>>>(lv, prec, Dout, Tout);
}

// round 4
// speedup vs baseline: 1.8902x; 1.0611x over previous
#include <cuda_runtime.h>
#include <cuda_bf16.h>
#include <math.h>
#include <stdint.h>

#define BATCH 8192
#define HID   1024
#define FH    96
#define O_DIM 8
#define E_DIM 36
#define NM    768
#define NV    3456

// ---------------------------------------------------------------------------
// Device scratch (allocation-free per harness rules)
// ---------------------------------------------------------------------------
__device__ __nv_bfloat16 g_zhi[(size_t)BATCH * HID];
__device__ __nv_bfloat16 g_zlo[(size_t)BATCH * HID];
__device__ __nv_bfloat16 g_ihi[(size_t)BATCH * HID];
__device__ __nv_bfloat16 g_ilo[(size_t)BATCH * HID];
__device__ __nv_bfloat16 g_hhi[(size_t)BATCH * HID];
__device__ __nv_bfloat16 g_hlo[(size_t)BATCH * HID];
__device__ __nv_bfloat16 g_w1hi[(size_t)HID * HID];
__device__ __nv_bfloat16 g_w1lo[(size_t)HID * HID];
__device__ __nv_bfloat16 g_w2hi[(size_t)HID * HID];
__device__ __nv_bfloat16 g_w2lo[(size_t)HID * HID];
__device__ __nv_bfloat16 g_wmhi[(size_t)NM * HID];
__device__ __nv_bfloat16 g_wmlo[(size_t)NM * HID];
__device__ __nv_bfloat16 g_wvhi[(size_t)NV * HID];
__device__ __nv_bfloat16 g_wvlo[(size_t)NV * HID];
__device__ float         g_lv[(size_t)BATCH * NV];

// ---------------------------------------------------------------------------
// helpers
// ---------------------------------------------------------------------------
__device__ __forceinline__ uint32_t smem_u32(const void* p) {
    uint32_t a;
    asm("{ .reg .u64 t; cvta.to.shared.u64 t, %1; cvt.u32.u64 %0, t; }" : "=r"(a) : "l"(p));
    return a;
}

__device__ __forceinline__ void cp16(uint32_t dst, const void* src) {
    asm volatile("cp.async.cg.shared.global [%0], [%1], 16;" :: "r"(dst), "l"(src));
}
#define CP_COMMIT() asm volatile("cp.async.commit_group;" ::: "memory")
#define CP_WAIT0()  asm volatile("cp.async.wait_group 0;"  ::: "memory")

__device__ __forceinline__ void mma16816(float* d, const uint32_t* a, const uint32_t* b)
{
    asm volatile(
        "mma.sync.aligned.m16n8k16.row.col.f32.bf16.bf16.f32 "
        "{%0,%1,%2,%3},{%4,%5,%6,%7},{%8,%9},{%0,%1,%2,%3};\n"
        : "+f"(d[0]), "+f"(d[1]), "+f"(d[2]), "+f"(d[3])
        : "r"(a[0]), "r"(a[1]), "r"(a[2]), "r"(a[3]), "r"(b[0]), "r"(b[1]));
}

__device__ __forceinline__ uint32_t bfpack2(float a, float b) {
    __nv_bfloat162 t = __halves2bfloat162(__float2bfloat16(a), __float2bfloat16(b));
    return *reinterpret_cast<uint32_t*>(&t);
}

// ---------------------------------------------------------------------------
// split_act: fp32 [n] -> hi bf16 [n], lo bf16 [n]
// ---------------------------------------------------------------------------
__global__ __launch_bounds__(256)
void split_act(const float* __restrict__ x,
               __nv_bfloat16* __restrict__ hi, __nv_bfloat16* __restrict__ lo)
{
    size_t idx = ((size_t)blockIdx.x * blockDim.x + threadIdx.x) * 4;
    float4 v = *(const float4*)(x + idx);
    __nv_bfloat16 h0 = __float2bfloat16(v.x), h1 = __float2bfloat16(v.y);
    __nv_bfloat16 h2 = __float2bfloat16(v.z), h3 = __float2bfloat16(v.w);
    uint2 hp, lp;
    { __nv_bfloat162 a = __halves2bfloat162(h0, h1), b = __halves2bfloat162(h2, h3);
      hp.x = *(uint32_t*)&a; hp.y = *(uint32_t*)&b; }
    lp.x = bfpack2(v.x - __bfloat162float(h0), v.y - __bfloat162float(h1));
    lp.y = bfpack2(v.z - __bfloat162float(h2), v.w - __bfloat162float(h3));
    *(uint2*)(hi + idx) = hp;
    *(uint2*)(lo + idx) = lp;
}

// ---------------------------------------------------------------------------
// split_w: W fp32 [K, N] -> Wt hi/lo bf16 [N, K] (transposed + split)
// ---------------------------------------------------------------------------
__global__ __launch_bounds__(256)
void split_w(const float* __restrict__ W,
             __nv_bfloat16* __restrict__ Whi, __nv_bfloat16* __restrict__ Wlo,
             int K, int N)
{
    __shared__ float tile[32][33];
    const int k0 = blockIdx.y * 32, n0 = blockIdx.x * 32;
    const int tx = threadIdx.x & 31, ty = threadIdx.x >> 5;
#pragma unroll
    for (int r = ty; r < 32; r += 8)
        tile[r][tx] = W[(size_t)(k0 + r) * N + n0 + tx];
    __syncthreads();
#pragma unroll
    for (int i = threadIdx.x; i < 32 * 16; i += 256) {
        int nl = i >> 4, kp = i & 15;
        float a = tile[2 * kp][nl], b = tile[2 * kp + 1][nl];
        __nv_bfloat16 ha = __float2bfloat16(a), hb = __float2bfloat16(b);
        size_t base = (size_t)(n0 + nl) * K + k0 + 2 * kp;
        *(uint32_t*)(Whi + base) = bfpack2(a, b);
        *(uint32_t*)(Wlo + base) = bfpack2(a - __bfloat162float(ha), b - __bfloat162float(hb));
    }
}

// ---------------------------------------------------------------------------
// bf16x3 GEMM, pre-split inputs: C[M,N] = act(A @ Bt^T + bias)
// A given as Ahi/Alo [M,K] bf16; Bt as Bthi/Btlo [N,K] bf16. K = HID = 1024.
// CTA 256x128, BK=16, 8 warps (4M x 2N), warp tile 64x64, cp.async staging.
// OUTMODE 0: fp32 out Cf. OUTMODE 1: bf16 hi/lo out (Chi/Clo).
// ---------------------------------------------------------------------------
template <bool SILU, int OUTMODE>
__global__ __launch_bounds__(256, 1)
void gemm_mma(int N,
              const __nv_bfloat16* __restrict__ Ahi, const __nv_bfloat16* __restrict__ Alo,
              const __nv_bfloat16* __restrict__ Bthi, const __nv_bfloat16* __restrict__ Btlo,
              const float* __restrict__ bias,
              float* __restrict__ Cf,
              __nv_bfloat16* __restrict__ Chi, __nv_bfloat16* __restrict__ Clo)
{
    constexpr int K = HID;
    constexpr int NITER = K / 16;          // 64
    constexpr int RS = 48;                 // row stride bytes (16 bf16 = 32B + 16B pad)
    constexpr int SA_HI = 0;
    constexpr int SA_LO = 256 * RS;        // 12288
    constexpr int SB_HI = 2 * 256 * RS;    // 24576
    constexpr int SB_LO = SB_HI + 128 * RS;// 30720
    constexpr int STAGE = SB_LO + 128 * RS;// 36864
    constexpr int BIASOFF = 2 * STAGE;     // 73728

    extern __shared__ __align__(128) char smem[];
    const uint32_t sb = smem_u32(smem);
    float* sBias = (float*)(smem + BIASOFF);

    const int tid  = threadIdx.x;
    const int lane = tid & 31;
    const int wid  = tid >> 5;
    const int g = lane >> 2;               // 0..7
    const int t = lane & 3;                // 0..3
    const int warpM = wid & 3;             // 4 along M
    const int warpN = wid >> 2;            // 2 along N
    const int m0 = warpM * 64;
    const int n0 = warpN * 64;

    const int blockM = blockIdx.y * 256;
    const int blockN = blockIdx.x * 128;

    if (tid < 128) sBias[tid] = bias[blockN + tid];

    // Per-thread copy mapping
    const int arow0 = tid >> 1;            // A chunk pair base (idx = tid + 256j)
    const int ach0  = tid & 1;
    const int brow  = tid >> 1;            // B: 256 chunks
    const int bch   = tid & 1;

    const __nv_bfloat16* Ahi_b = Ahi + (size_t)blockM * K;
    const __nv_bfloat16* Alo_b = Alo + (size_t)blockM * K;
    const __nv_bfloat16* Bhi_b = Bthi + (size_t)blockN * K;
    const __nv_bfloat16* Blo_b = Btlo + (size_t)blockN * K;

    auto load_stage = [&](int s) {
        const int k0 = s * 16;
        const uint32_t buf = sb + (s & 1) * STAGE;
#pragma unroll
        for (int j = 0; j < 2; j++) {
            const int idx = tid + 256 * j;
            const int row = idx >> 1, ch = idx & 1;
            const size_t goff = (size_t)row * K + k0 + ch * 8;
            const uint32_t soff = row * RS + ch * 16;
            cp16(buf + SA_HI + soff, Ahi_b + goff);
            cp16(buf + SA_LO + soff, Alo_b + goff);
        }
        {
            const size_t goff = (size_t)brow * K + k0 + bch * 8;
            const uint32_t soff = brow * RS + bch * 16;
            cp16(buf + SB_HI + soff, Bhi_b + goff);
            cp16(buf + SB_LO + soff, Blo_b + goff);
        }
    };

    float acc[4][8][4];
#pragma unroll
    for (int mt = 0; mt < 4; mt++)
#pragma unroll
        for (int nt = 0; nt < 8; nt++)
#pragma unroll
            for (int c = 0; c < 4; c++) acc[mt][nt][c] = 0.f;

    load_stage(0);
    CP_COMMIT();

    for (int it = 0; it < NITER; ++it) {
        CP_WAIT0();
        __syncthreads();
        if (it + 1 < NITER) { load_stage(it + 1); CP_COMMIT(); }

        const uint32_t buf = sb + (it & 1) * STAGE;
        const uint32_t aHi = buf + SA_HI, aLo = buf + SA_LO;
        const uint32_t bHi = buf + SB_HI, bLo = buf + SB_LO;

        uint32_t fAhi[4][4], fAlo[4][4], fB[8][2];
#pragma unroll
        for (int mt = 0; mt < 4; mt++) {
            const int r = m0 + mt * 16;
            const uint32_t o0 = (r + g) * RS + t * 4;
            const uint32_t o1 = (r + g + 8) * RS + t * 4;
            asm volatile("ld.shared.b32 %0, [%1];" : "=r"(fAhi[mt][0]) : "r"(aHi + o0));
            asm volatile("ld.shared.b32 %0, [%1];" : "=r"(fAhi[mt][1]) : "r"(aHi + o1));
            asm volatile("ld.shared.b32 %0, [%1];" : "=r"(fAhi[mt][2]) : "r"(aHi + o0 + 16));
            asm volatile("ld.shared.b32 %0, [%1];" : "=r"(fAhi[mt][3]) : "r"(aHi + o1 + 16));
            asm volatile("ld.shared.b32 %0, [%1];" : "=r"(fAlo[mt][0]) : "r"(aLo + o0));
            asm volatile("ld.shared.b32 %0, [%1];" : "=r"(fAlo[mt][1]) : "r"(aLo + o1));
            asm volatile("ld.shared.b32 %0, [%1];" : "=r"(fAlo[mt][2]) : "r"(aLo + o0 + 16));
            asm volatile("ld.shared.b32 %0, [%1];" : "=r"(fAlo[mt][3]) : "r"(aLo + o1 + 16));
        }
#pragma unroll
        for (int nt = 0; nt < 8; nt++) {
            const uint32_t o = (n0 + nt * 8 + g) * RS + t * 4;
            asm volatile("ld.shared.b32 %0, [%1];" : "=r"(fB[nt][0]) : "r"(bHi + o));
            asm volatile("ld.shared.b32 %0, [%1];" : "=r"(fB[nt][1]) : "r"(bHi + o + 16));
        }
        // pass 1: hi * hi ; pass 2: lo_A * hi_B
#pragma unroll
        for (int mt = 0; mt < 4; mt++)
#pragma unroll
            for (int nt = 0; nt < 8; nt++) {
                mma16816(acc[mt][nt], fAhi[mt], fB[nt]);
                mma16816(acc[mt][nt], fAlo[mt], fB[nt]);
            }
        // reload B lo, pass 3: hi_A * lo_B
#pragma unroll
        for (int nt = 0; nt < 8; nt++) {
            const uint32_t o = (n0 + nt * 8 + g) * RS + t * 4;
            asm volatile("ld.shared.b32 %0, [%1];" : "=r"(fB[nt][0]) : "r"(bLo + o));
            asm volatile("ld.shared.b32 %0, [%1];" : "=r"(fB[nt][1]) : "r"(bLo + o + 16));
        }
#pragma unroll
        for (int mt = 0; mt < 4; mt++)
#pragma unroll
            for (int nt = 0; nt < 8; nt++)
                mma16816(acc[mt][nt], fAhi[mt], fB[nt]);
    }

    // epilogue
#pragma unroll
    for (int mt = 0; mt < 4; mt++) {
        const int row0 = blockM + m0 + mt * 16 + g;
#pragma unroll
        for (int nt = 0; nt < 8; nt++) {
            const int coll = n0 + nt * 8 + 2 * t;
            const int col  = blockN + coll;
            const float bv0 = sBias[coll], bv1 = sBias[coll + 1];
            float v00 = acc[mt][nt][0] + bv0, v01 = acc[mt][nt][1] + bv1;
            float v10 = acc[mt][nt][2] + bv0, v11 = acc[mt][nt][3] + bv1;
            if (SILU) {
                v00 = v00 / (1.f + expf(-v00));
                v01 = v01 / (1.f + expf(-v01));
                v10 = v10 / (1.f + expf(-v10));
                v11 = v11 / (1.f + expf(-v11));
            }
            if (OUTMODE == 0) {
                float2 a = {v00, v01}, b = {v10, v11};
                *(float2*)(Cf + (size_t)row0 * N + col)       = a;
                *(float2*)(Cf + (size_t)(row0 + 8) * N + col) = b;
            } else {
                __nv_bfloat16 h00 = __float2bfloat16(v00), h01 = __float2bfloat16(v01);
                __nv_bfloat16 h10 = __float2bfloat16(v10), h11 = __float2bfloat16(v11);
                size_t p0 = (size_t)row0 * K + col;
                size_t p1 = (size_t)(row0 + 8) * K + col;
                { __nv_bfloat162 x = __halves2bfloat162(h00, h01);
                  *(uint32_t*)(Chi + p0) = *(uint32_t*)&x; }
                { __nv_bfloat162 x = __halves2bfloat162(h10, h11);
                  *(uint32_t*)(Chi + p1) = *(uint32_t*)&x; }
                *(uint32_t*)(Clo + p0) = bfpack2(v00 - __bfloat162float(h00), v01 - __bfloat162float(h01));
                *(uint32_t*)(Clo + p1) = bfpack2(v10 - __bfloat162float(h10), v11 - __bfloat162float(h11));
            }
        }
    }
}

// ---------------------------------------------------------------------------
// MVN epilogue
// ---------------------------------------------------------------------------
__device__ __forceinline__ int triu_idx(int r, int c) {
    return r * (15 - r) / 2 + (c - r - 1);
}

__global__ __launch_bounds__(256)
void mvn_epilogue(const float* __restrict__ lv,
                  float* __restrict__ prec,
                  float* __restrict__ Dout,
                  float* __restrict__ Tout)
{
    constexpr int GP = 4;
    __shared__ float s_eta[GP][E_DIM];
    __shared__ float s_d[GP][O_DIM];
    __shared__ float s_dinv[GP][O_DIM];

    const int g = threadIdx.x >> 6;
    const int t = threadIdx.x & 63;
    const size_t bh = (size_t)blockIdx.x * GP + g;

    if (t < E_DIM) s_eta[g][t] = lv[bh * E_DIM + t];
    __syncthreads();
    if (t < O_DIM) {
        float d = expf(0.5f * s_eta[g][t]);
        s_d[g][t] = d;
        s_dinv[g][t] = 1.f / d;
    }
    __syncthreads();

    const int i = t >> 3, k = t & 7;
    const float* e = s_eta[g];
    const float* dinv = s_dinv[g];

    float tv = (i == k) ? 1.f : ((i < k) ? e[O_DIM + triu_idx(i, k)] : 0.f);
    float dv = (i == k) ? s_d[g][i] : 0.f;
    float s = 0.f;
#pragma unroll
    for (int j = 0; j < O_DIM; j++) {
        float tji = (j == i) ? 1.f : ((j < i) ? e[O_DIM + triu_idx(j, i)] : 0.f);
        float tjk = (j == k) ? 1.f : ((j < k) ? e[O_DIM + triu_idx(j, k)] : 0.f);
        s = fmaf(tji * tjk, dinv[j], s);
    }

    const size_t base = bh * (O_DIM * O_DIM) + t;
    prec[base] = s;
    Dout[base] = dv;
    Tout[base] = tv;
}

// ---------------------------------------------------------------------------
// Launch
// ---------------------------------------------------------------------------
extern "C" void kernel_launch(void* const* d_in, const int* in_sizes, int n_in,
                              void* d_out, int out_size)
{
    const float* z  = (const float*)d_in[0];
    const float* W1 = (const float*)d_in[1];
    const float* b1 = (const float*)d_in[2];
    const float* W2 = (const float*)d_in[3];
    const float* b2 = (const float*)d_in[4];
    const float* Wm = (const float*)d_in[5];
    const float* bm = (const float*)d_in[6];
    const float* Wv = (const float*)d_in[7];
    const float* bv = (const float*)d_in[8];

    float* out = (float*)d_out;
    const size_t n_means = (size_t)BATCH * FH * O_DIM;
    const size_t n_mat   = (size_t)BATCH * FH * O_DIM * O_DIM;
    float* means = out;
    float* prec  = out + n_means;
    float* Dout  = prec + n_mat;
    float* Tout  = Dout + n_mat;

    __nv_bfloat16 *zhi, *zlo, *ihi, *ilo, *hhi, *hlo;
    __nv_bfloat16 *w1hi, *w1lo, *w2hi, *w2lo, *wmhi, *wmlo, *wvhi, *wvlo;
    float* lv;
    cudaGetSymbolAddress((void**)&zhi, g_zhi);   cudaGetSymbolAddress((void**)&zlo, g_zlo);
    cudaGetSymbolAddress((void**)&ihi, g_ihi);   cudaGetSymbolAddress((void**)&ilo, g_ilo);
    cudaGetSymbolAddress((void**)&hhi, g_hhi);   cudaGetSymbolAddress((void**)&hlo, g_hlo);
    cudaGetSymbolAddress((void**)&w1hi, g_w1hi); cudaGetSymbolAddress((void**)&w1lo, g_w1lo);
    cudaGetSymbolAddress((void**)&w2hi, g_w2hi); cudaGetSymbolAddress((void**)&w2lo, g_w2lo);
    cudaGetSymbolAddress((void**)&wmhi, g_wmhi); cudaGetSymbolAddress((void**)&wmlo, g_wmlo);
    cudaGetSymbolAddress((void**)&wvhi, g_wvhi); cudaGetSymbolAddress((void**)&wvlo, g_wvlo);
    cudaGetSymbolAddress((void**)&lv, g_lv);

    const int SMEM_BYTES = 2 * 36864 + 512;   // 74240
    cudaFuncSetAttribute((void*)gemm_mma<true, 1>,  cudaFuncAttributeMaxDynamicSharedMemorySize, SMEM_BYTES);
    cudaFuncSetAttribute((void*)gemm_mma<false, 1>, cudaFuncAttributeMaxDynamicSharedMemorySize, SMEM_BYTES);
    cudaFuncSetAttribute((void*)gemm_mma<false, 0>, cudaFuncAttributeMaxDynamicSharedMemorySize, SMEM_BYTES);

    // converts
    split_act<<<(BATCH * HID / 4) / 256, 256>>>(z, zhi, zlo);
    split_w<<<dim3(HID / 32, HID / 32), 256>>>(W1, w1hi, w1lo, HID, HID);
    split_w<<<dim3(HID / 32, HID / 32), 256>>>(W2, w2hi, w2lo, HID, HID);
    split_w<<<dim3(NM  / 32, HID / 32), 256>>>(Wm, wmhi, wmlo, HID, NM);
    split_w<<<dim3(NV  / 32, HID / 32), 256>>>(Wv, wvhi, wvlo, HID, NV);

    // GEMM chain
    gemm_mma<true, 1><<<dim3(HID / 128, BATCH / 256), 256, SMEM_BYTES>>>(
        HID, zhi, zlo, w1hi, w1lo, b1, nullptr, ihi, ilo);
    gemm_mma<false, 1><<<dim3(HID / 128, BATCH / 256), 256, SMEM_BYTES>>>(
        HID, ihi, ilo, w2hi, w2lo, b2, nullptr, hhi, hlo);
    gemm_mma<false, 0><<<dim3(NM / 128, BATCH / 256), 256, SMEM_BYTES>>>(
        NM, hhi, hlo, wmhi, wmlo, bm, means, nullptr, nullptr);
    gemm_mma<false, 0><<<dim3(NV / 128, BATCH / 256), 256, SMEM_BYTES>>>(
        NV, hhi, hlo, wvhi, wvlo, bv, lv, nullptr, nullptr);

    mvn_epilogue<<<(BATCH * FH) / 4, 256>>>(lv, prec, Dout, Tout);
}